// round 1
// baseline (speedup 1.0000x reference)
#include <cuda_runtime.h>

// GridSampler3D: vol [N=8, C=32, D=64, H=64, W=64] fp32, grid [8,64,64,64,3] in [-1,1],
// trilinear, zeros padding, align_corners=True. Output [8,32,64,64,64] fp32.
//
// Strategy:
//   Pass 1: transpose vol NCDHW -> NDHWC into a __device__ scratch (channels contiguous,
//           128B-aligned per voxel) so each random gather pulls 8x128B instead of 8x32x32B.
//   Pass 2: one thread per output spatial point; compute 8 corner weights once, accumulate
//           all 32 channels in registers via float4 loads; coalesced strided writes.

#define Nn 8
#define Cc 32
#define Dd 64
#define Hh 64
#define Ww 64
#define S  (Dd * Hh * Ww)   // 262144 = 2^18

// 256 MB scratch for the channel-last volume (allowed: __device__ global array).
__device__ float g_volt[(size_t)Nn * S * Cc];

// ---------------------------------------------------------------------------
// Pass 1: [N, C, S] -> [N, S, C] tiled transpose (32x32 tiles through smem).
// Reads coalesced along S, writes coalesced along C.
// ---------------------------------------------------------------------------
__global__ void __launch_bounds__(1024) transpose_nchw_to_nhwc(const float* __restrict__ vol) {
    __shared__ float tile[32][33];
    const int n  = blockIdx.y;
    const int s0 = blockIdx.x << 5;
    const int tx = threadIdx.x;
    const int ty = threadIdx.y;

    // load: channel = ty, spatial = s0 + tx  (consecutive tx -> coalesced)
    tile[ty][tx] = vol[((size_t)n * Cc + ty) * S + (s0 + tx)];
    __syncthreads();
    // store: spatial = s0 + ty, channel = tx (consecutive tx -> coalesced)
    g_volt[((size_t)n * S + (s0 + ty)) * Cc + tx] = tile[tx][ty];
}

// ---------------------------------------------------------------------------
// Pass 2: gather + trilinear blend. One thread per output spatial point.
// ---------------------------------------------------------------------------
__global__ void __launch_bounds__(256) grid_sample3d_kernel(const float* __restrict__ grid,
                                                            float* __restrict__ out) {
    const int t = blockIdx.x * 256 + threadIdx.x;   // t in [0, N*S)
    const int n = t >> 18;                          // S = 2^18
    const int s = t & (S - 1);

    const float gx = grid[(size_t)t * 3 + 0];
    const float gy = grid[(size_t)t * 3 + 1];
    const float gz = grid[(size_t)t * 3 + 2];

    // align_corners=True: [-1,1] -> [0, size-1]
    const float ix = (gx + 1.0f) * (0.5f * (Ww - 1));
    const float iy = (gy + 1.0f) * (0.5f * (Hh - 1));
    const float iz = (gz + 1.0f) * (0.5f * (Dd - 1));

    const float fx = floorf(ix);
    const float fy = floorf(iy);
    const float fz = floorf(iz);
    const int x0 = (int)fx, y0 = (int)fy, z0 = (int)fz;
    const float wx1 = ix - fx, wy1 = iy - fy, wz1 = iz - fz;

    const int   xs[2]  = {x0, x0 + 1};
    const int   ys[2]  = {y0, y0 + 1};
    const int   zs[2]  = {z0, z0 + 1};
    const float wxs[2] = {1.0f - wx1, wx1};
    const float wys[2] = {1.0f - wy1, wy1};
    const float wzs[2] = {1.0f - wz1, wz1};

    float acc[32];
    #pragma unroll
    for (int c = 0; c < 32; c++) acc[c] = 0.0f;

    const float* __restrict__ vt = g_volt + (size_t)n * S * Cc;

    #pragma unroll
    for (int k = 0; k < 8; k++) {
        const int zi = zs[k >> 2];
        const int yi = ys[(k >> 1) & 1];
        const int xi = xs[k & 1];
        const float w = wzs[k >> 2] * wys[(k >> 1) & 1] * wxs[k & 1];
        // zeros padding: skip out-of-bounds corners entirely
        if ((unsigned)zi < Dd && (unsigned)yi < Hh && (unsigned)xi < Ww) {
            const float4* __restrict__ p =
                (const float4*)(vt + ((((size_t)zi * Hh + yi) * Ww + xi) << 5));  // *Cc
            #pragma unroll
            for (int j = 0; j < 8; j++) {
                const float4 v = p[j];
                acc[4 * j + 0] = fmaf(w, v.x, acc[4 * j + 0]);
                acc[4 * j + 1] = fmaf(w, v.y, acc[4 * j + 1]);
                acc[4 * j + 2] = fmaf(w, v.z, acc[4 * j + 2]);
                acc[4 * j + 3] = fmaf(w, v.w, acc[4 * j + 3]);
            }
        }
    }

    // out[n, c, s]: for fixed c, the warp's lanes (adjacent s) write one 128B line.
    float* __restrict__ o = out + (size_t)n * Cc * S + s;
    #pragma unroll
    for (int c = 0; c < 32; c++) o[(size_t)c * S] = acc[c];
}

extern "C" void kernel_launch(void* const* d_in, const int* in_sizes, int n_in,
                              void* d_out, int out_size) {
    const float* vol  = (const float*)d_in[0];   // [8,32,64,64,64]
    const float* grid = (const float*)d_in[1];   // [8,64,64,64,3]
    float* out = (float*)d_out;                  // [8,32,64,64,64]

    dim3 tb(32, 32);
    dim3 tg(S / 32, Nn);
    transpose_nchw_to_nhwc<<<tg, tb>>>(vol);

    const int total = Nn * S;                    // 2,097,152
    grid_sample3d_kernel<<<total / 256, 256>>>(grid, out);
}

// round 2
// speedup vs baseline: 2.7667x; 2.7667x over previous
#include <cuda_runtime.h>

// GridSampler3D: vol [8,32,64,64,64] fp32, grid [8,64,64,64,3], trilinear,
// zeros padding, align_corners=True. Output [8,32,64,64,64] fp32.
//
// Pass 1: NCDHW -> NDHWC transpose into __device__ scratch (channels contiguous,
//         128B per voxel), vectorized, ~2 elems of ILP per thread per phase.
// Pass 2: 8 lanes per output point, each lane owns 4 channels (float4).
//         Each corner load is one fully-consumed 128B line per point
//         (4 L1 wavefronts per warp instr instead of 32). Output staged in
//         smem tile and written channel-major fully coalesced.

#define Nn 8
#define Cc 32
#define Dd 64
#define Hh 64
#define Ww 64
#define S  (Dd * Hh * Ww)   // 262144 = 2^18

__device__ float g_volt[(size_t)Nn * S * Cc];   // 256 MB channel-last scratch

// ---------------------------------------------------------------------------
// Pass 1 transpose: block = 256 threads handles 64 spatial x 32 channels.
// ---------------------------------------------------------------------------
__global__ void __launch_bounds__(256) transpose_nchw_to_nhwc(const float* __restrict__ vol) {
    __shared__ float tile[64][33];
    const int n  = blockIdx.y;
    const int s0 = blockIdx.x << 6;          // 64 spatial per block
    const int tid = threadIdx.x;

    // Load: 512 float4 reads along S (coalesced). i -> c = i/16, s4 = i%16.
    {
        const int c  = tid >> 4;             // 0..15  (first half of channels)
        const int s4 = tid & 15;             // 0..15
        #pragma unroll
        for (int half = 0; half < 2; half++) {
            const int ch = c + half * 16;
            const float4 v = *(const float4*)(vol + ((size_t)n * Cc + ch) * S + s0 + s4 * 4);
            tile[s4 * 4 + 0][ch] = v.x;
            tile[s4 * 4 + 1][ch] = v.y;
            tile[s4 * 4 + 2][ch] = v.z;
            tile[s4 * 4 + 3][ch] = v.w;
        }
    }
    __syncthreads();

    // Store: 512 float4 writes along C (coalesced). i -> s = i/8, c4 = i%8.
    {
        const int s  = tid >> 3;             // 0..31 (first half of spatial)
        const int c4 = tid & 7;              // 0..7
        #pragma unroll
        for (int half = 0; half < 2; half++) {
            const int sp = s + half * 32;
            float4 v;
            v.x = tile[sp][c4 * 4 + 0];
            v.y = tile[sp][c4 * 4 + 1];
            v.z = tile[sp][c4 * 4 + 2];
            v.w = tile[sp][c4 * 4 + 3];
            *(float4*)(g_volt + ((size_t)n * S + s0 + sp) * Cc + c4 * 4) = v;
        }
    }
}

// ---------------------------------------------------------------------------
// Pass 2: gather. Block = 256 threads = 32 points; 8 lanes per point,
// each lane accumulates 4 channels.
// ---------------------------------------------------------------------------
__global__ void __launch_bounds__(256) grid_sample3d_kernel(const float* __restrict__ grid,
                                                            float* __restrict__ out) {
    __shared__ float tile[32][37];           // [point][channel], pad 37 (odd-ish stride, conflict-free writes)

    const int tid = threadIdx.x;
    const int pl  = tid >> 3;                // point-in-block 0..31
    const int c4  = tid & 7;                 // channel quad 0..7

    const int t = blockIdx.x * 32 + pl;      // global point id in [0, N*S)
    const int n = t >> 18;                   // S = 2^18
    const int s = t & (S - 1);

    const float gx = grid[(size_t)t * 3 + 0];
    const float gy = grid[(size_t)t * 3 + 1];
    const float gz = grid[(size_t)t * 3 + 2];

    const float ix = (gx + 1.0f) * (0.5f * (Ww - 1));
    const float iy = (gy + 1.0f) * (0.5f * (Hh - 1));
    const float iz = (gz + 1.0f) * (0.5f * (Dd - 1));

    const float fx = floorf(ix), fy = floorf(iy), fz = floorf(iz);
    const int x0 = (int)fx, y0 = (int)fy, z0 = (int)fz;
    const float wx1 = ix - fx, wy1 = iy - fy, wz1 = iz - fz;

    const int   xs[2]  = {x0, x0 + 1};
    const int   ys[2]  = {y0, y0 + 1};
    const int   zs[2]  = {z0, z0 + 1};
    const float wxs[2] = {1.0f - wx1, wx1};
    const float wys[2] = {1.0f - wy1, wy1};
    const float wzs[2] = {1.0f - wz1, wz1};

    float ax = 0.0f, ay = 0.0f, az = 0.0f, aw = 0.0f;

    const float* __restrict__ vt = g_volt + ((size_t)n * S) * Cc;

    #pragma unroll
    for (int k = 0; k < 8; k++) {
        const int zi = zs[k >> 2];
        const int yi = ys[(k >> 1) & 1];
        const int xi = xs[k & 1];
        const float w = wzs[k >> 2] * wys[(k >> 1) & 1] * wxs[k & 1];
        if ((unsigned)zi < Dd && (unsigned)yi < Hh && (unsigned)xi < Ww) {
            const float4 v = *(const float4*)(vt + ((((size_t)zi * Hh + yi) * Ww + xi) << 5) + c4 * 4);
            ax = fmaf(w, v.x, ax);
            ay = fmaf(w, v.y, ay);
            az = fmaf(w, v.z, az);
            aw = fmaf(w, v.w, aw);
        }
    }

    tile[pl][c4 * 4 + 0] = ax;
    tile[pl][c4 * 4 + 1] = ay;
    tile[pl][c4 * 4 + 2] = az;
    tile[pl][c4 * 4 + 3] = aw;
    __syncthreads();

    // Write out[n, c, s0 + tx]: 32 consecutive points per channel -> coalesced 128B.
    const int tx = tid & 31;                 // point offset
    const int ty = tid >> 5;                 // channel base 0..7
    const int s0 = s & ~31;                  // block's first spatial index
    float* __restrict__ o = out + (size_t)n * Cc * S + s0 + tx;
    #pragma unroll
    for (int rep = 0; rep < 4; rep++) {
        const int ch = ty + rep * 8;
        o[(size_t)ch * S] = tile[tx][ch];
    }
}

extern "C" void kernel_launch(void* const* d_in, const int* in_sizes, int n_in,
                              void* d_out, int out_size) {
    const float* vol  = (const float*)d_in[0];
    const float* grid = (const float*)d_in[1];
    float* out = (float*)d_out;

    dim3 tg(S / 64, Nn);
    transpose_nchw_to_nhwc<<<tg, 256>>>(vol);

    const int total = Nn * S;                // 2,097,152 points
    grid_sample3d_kernel<<<total / 32, 256>>>(grid, out);
}

// round 3
// speedup vs baseline: 3.4833x; 1.2590x over previous
#include <cuda_runtime.h>
#include <cuda_fp16.h>

// GridSampler3D: vol [8,32,64,64,64] fp32, grid [8,64,64,64,3], trilinear,
// zeros padding, align_corners=True. Output [8,32,64,64,64] fp32.
//
// Pass 1: NCDHW fp32 -> NDHWC fp16 transpose (halves all downstream traffic).
// Pass 2: 4 lanes per output point, each lane owns 8 channels (one 16B uint4
//         of halves per corner). fp32 accumulation. Smem-staged coalesced writes.

#define Nn 8
#define Cc 32
#define Dd 64
#define Hh 64
#define Ww 64
#define S  (Dd * Hh * Ww)   // 262144 = 2^18

__device__ __half g_volt[(size_t)Nn * S * Cc];   // 128 MB channel-last fp16 scratch

// ---------------------------------------------------------------------------
// Pass 1: block = 256 threads handles 64 spatial x 32 channels.
// ---------------------------------------------------------------------------
__global__ void __launch_bounds__(256) transpose_to_nhwc_h(const float* __restrict__ vol) {
    __shared__ float tile[64][33];
    const int n   = blockIdx.y;
    const int s0  = blockIdx.x << 6;         // 64 spatial per block
    const int tid = threadIdx.x;

    // Load: float4 along S (coalesced).
    {
        const int c  = tid >> 4;             // 0..15
        const int s4 = tid & 15;             // 0..15
        #pragma unroll
        for (int half_i = 0; half_i < 2; half_i++) {
            const int ch = c + half_i * 16;
            const float4 v = *(const float4*)(vol + ((size_t)n * Cc + ch) * S + s0 + s4 * 4);
            tile[s4 * 4 + 0][ch] = v.x;
            tile[s4 * 4 + 1][ch] = v.y;
            tile[s4 * 4 + 2][ch] = v.z;
            tile[s4 * 4 + 3][ch] = v.w;
        }
    }
    __syncthreads();

    // Store: 4 halves (8B) per thread per phase, coalesced along C.
    {
        const int s  = tid >> 3;             // 0..31
        const int c4 = tid & 7;              // 0..7
        #pragma unroll
        for (int half_i = 0; half_i < 2; half_i++) {
            const int sp = s + half_i * 32;
            __half2 h0 = __floats2half2_rn(tile[sp][c4 * 4 + 0], tile[sp][c4 * 4 + 1]);
            __half2 h1 = __floats2half2_rn(tile[sp][c4 * 4 + 2], tile[sp][c4 * 4 + 3]);
            uint2 pk;
            pk.x = *(unsigned*)&h0;
            pk.y = *(unsigned*)&h1;
            *(uint2*)(g_volt + ((size_t)n * S + s0 + sp) * Cc + c4 * 4) = pk;
        }
    }
}

// ---------------------------------------------------------------------------
// Pass 2: gather. Block = 256 threads = 64 points; 4 lanes per point,
// each lane accumulates 8 channels in fp32.
// ---------------------------------------------------------------------------
__global__ void __launch_bounds__(256) grid_sample3d_kernel(const float* __restrict__ grid,
                                                            float* __restrict__ out) {
    __shared__ float tile[64][33];           // [point][channel]

    const int tid = threadIdx.x;
    const int pl  = tid >> 2;                // point-in-block 0..63
    const int c4  = tid & 3;                 // channel octet 0..3

    const int t = blockIdx.x * 64 + pl;      // global point id
    const int n = t >> 18;                   // S = 2^18
    // block never straddles n (S % 64 == 0)

    const float gx = grid[(size_t)t * 3 + 0];
    const float gy = grid[(size_t)t * 3 + 1];
    const float gz = grid[(size_t)t * 3 + 2];

    const float ix = (gx + 1.0f) * (0.5f * (Ww - 1));
    const float iy = (gy + 1.0f) * (0.5f * (Hh - 1));
    const float iz = (gz + 1.0f) * (0.5f * (Dd - 1));

    const float fx = floorf(ix), fy = floorf(iy), fz = floorf(iz);
    const int x0 = (int)fx, y0 = (int)fy, z0 = (int)fz;
    const float wx1 = ix - fx, wy1 = iy - fy, wz1 = iz - fz;

    const int   xs[2]  = {x0, x0 + 1};
    const int   ys[2]  = {y0, y0 + 1};
    const int   zs[2]  = {z0, z0 + 1};
    const float wxs[2] = {1.0f - wx1, wx1};
    const float wys[2] = {1.0f - wy1, wy1};
    const float wzs[2] = {1.0f - wz1, wz1};

    float acc[8];
    #pragma unroll
    for (int j = 0; j < 8; j++) acc[j] = 0.0f;

    const __half* __restrict__ vt = g_volt + (size_t)n * S * Cc;

    #pragma unroll
    for (int k = 0; k < 8; k++) {
        const int zi = zs[k >> 2];
        const int yi = ys[(k >> 1) & 1];
        const int xi = xs[k & 1];
        const float w = wzs[k >> 2] * wys[(k >> 1) & 1] * wxs[k & 1];
        if ((unsigned)zi < Dd && (unsigned)yi < Hh && (unsigned)xi < Ww) {
            const uint4 raw = *(const uint4*)(vt + ((((size_t)zi * Hh + yi) * Ww + xi) << 5) + c4 * 8);
            const float2 f0 = __half22float2(*(const __half2*)&raw.x);
            const float2 f1 = __half22float2(*(const __half2*)&raw.y);
            const float2 f2 = __half22float2(*(const __half2*)&raw.z);
            const float2 f3 = __half22float2(*(const __half2*)&raw.w);
            acc[0] = fmaf(w, f0.x, acc[0]);
            acc[1] = fmaf(w, f0.y, acc[1]);
            acc[2] = fmaf(w, f1.x, acc[2]);
            acc[3] = fmaf(w, f1.y, acc[3]);
            acc[4] = fmaf(w, f2.x, acc[4]);
            acc[5] = fmaf(w, f2.y, acc[5]);
            acc[6] = fmaf(w, f3.x, acc[6]);
            acc[7] = fmaf(w, f3.y, acc[7]);
        }
    }

    #pragma unroll
    for (int j = 0; j < 8; j++) tile[pl][c4 * 8 + j] = acc[j];
    __syncthreads();

    // Write out[n, ch, s0 + p]: each warp covers 32 consecutive points for one
    // channel -> fully coalesced 128B stores.
    const int wv = tid >> 5;                 // warp 0..7
    const int ln = tid & 31;
    const int p  = (wv & 1) * 32 + ln;       // point 0..63
    const int chb = wv >> 1;                 // channel base 0..3
    const int s0 = (blockIdx.x * 64) & (S - 1);
    float* __restrict__ o = out + (size_t)n * Cc * S + s0 + p;
    #pragma unroll
    for (int rep = 0; rep < 8; rep++) {
        const int ch = chb + rep * 4;
        o[(size_t)ch * S] = tile[p][ch];
    }
}

extern "C" void kernel_launch(void* const* d_in, const int* in_sizes, int n_in,
                              void* d_out, int out_size) {
    const float* vol  = (const float*)d_in[0];
    const float* grid = (const float*)d_in[1];
    float* out = (float*)d_out;

    dim3 tg(S / 64, Nn);
    transpose_to_nhwc_h<<<tg, 256>>>(vol);

    const int total = Nn * S;                // 2,097,152 points
    grid_sample3d_kernel<<<total / 64, 256>>>(grid, out);
}